// round 16
// baseline (speedup 1.0000x reference)
#include <cuda_runtime.h>
#include <cuda_fp16.h>
#include <cuda_bf16.h>
#include <math.h>
#include <stdint.h>

#define S_LEN 2048
#define D_DIM 4096
#define H_NUM 32
#define HD    128
#define KDIM  4096

#if defined(__CUDA_ARCH__) && (defined(__CUDA_ARCH_FEAT_SM103_ALL) || defined(__CUDA_ARCH_FEAT_SM100_ALL) || defined(__CUDA_ARCH_SPECIFIC__) || defined(__CUDA_ARCH_FAMILY_SPECIFIC__))
#define USE_TC 1
#else
#define USE_TC 0
#endif

__device__ __nv_bfloat16 g_xa[S_LEN * D_DIM];
__device__ __nv_bfloat16 g_wb[4][D_DIM * D_DIM];
__device__ __nv_bfloat16 g_oa[S_LEN * D_DIM];
__device__ int    g_pint[3][S_LEN * D_DIM];
__device__ __nv_bfloat16 g_qb[H_NUM * S_LEN * HD];  // Q bf16 tiled [h*16+qt][32KB SW128]
__device__ __nv_bfloat16 g_kb[H_NUM * S_LEN * HD];  // K bf16 tiled
__device__ __half        g_vt[H_NUM * S_LEN * HD];  // V^T fp16 tiled [h*16+st][rows=d][cols=s]
__device__ float2 g_rope[S_LEN * 64];

__device__ __forceinline__ void cp_async16(void* smem, const void* gmem) {
    unsigned saddr = (unsigned)__cvta_generic_to_shared(smem);
    asm volatile("cp.async.cg.shared.global [%0], [%1], 16;\n" :: "r"(saddr), "l"(gmem));
}
__device__ __forceinline__ void cp_commit() { asm volatile("cp.async.commit_group;\n"); }
__device__ __forceinline__ int clampi(int v, int lo, int hi) { return max(lo, min(hi, v)); }
__device__ __forceinline__ uint32_t sw_off(int r, int c) {
    return (uint32_t)((r * 128 + c * 2) ^ ((r & 7) << 4));
}
__device__ __forceinline__ void splitpk2(float x0, float x1, uint32_t& hi, uint32_t& lo) {
    __half2 h = __floats2half2_rn(x0, x1);
    float2 f = __half22float2(h);
    __half2 e = __floats2half2_rn(x0 - f.x, x1 - f.y);
    hi = *(uint32_t*)&h;
    lo = *(uint32_t*)&e;
}
__device__ __forceinline__ uint32_t bfpack(int a, int b) {
    return (uint32_t)__bfloat16_as_ushort(__float2bfloat16_rn((float)a)) |
           ((uint32_t)__bfloat16_as_ushort(__float2bfloat16_rn((float)b)) << 16);
}
__device__ __forceinline__ float ex2f(float x) {
    float r;
    asm("ex2.approx.f32 %0, %1;" : "=f"(r) : "f"(x));
    return r;
}

#if USE_TC
__device__ __forceinline__ uint32_t smem_u32(const void* p) {
    uint32_t a;
    asm("{ .reg .u64 t; cvta.to.shared.u64 t, %1; cvt.u32.u64 %0, t; }" : "=r"(a) : "l"(p));
    return a;
}
#define MBARRIER_INIT(addr, cnt) \
    asm volatile("mbarrier.init.shared.b64 [%0], %1;" :: "r"((uint32_t)(addr)), "r"((uint32_t)(cnt)) : "memory")
#define MBARRIER_WAIT_PARITY(addr, ph) do {                                   \
    uint32_t _m = (uint32_t)(addr); uint32_t _p = (uint32_t)(ph);             \
    asm volatile("{\n\t.reg .pred P1;\n\t"                                    \
        "WL_%=:\n\t"                                                          \
        "mbarrier.try_wait.parity.acquire.cta.shared::cta.b64 P1, [%0], %1, 0x989680;\n\t" \
        "@P1 bra.uni WD_%=;\n\t"                                              \
        "bra.uni WL_%=;\n\t"                                                  \
        "WD_%=:\n\t}"                                                         \
        :: "r"(_m), "r"(_p) : "memory");                                      \
} while (0)
#define MBARRIER_EXPECT_TX(addr, bytes) \
    asm volatile("mbarrier.arrive.expect_tx.shared.b64 _, [%0], %1;" :: "r"((uint32_t)(addr)), "r"((uint32_t)(bytes)) : "memory")
#define TCGEN05_ALLOC(sma, n) \
    asm volatile("tcgen05.alloc.cta_group::1.sync.aligned.shared::cta.b32 [%0], %1;" \
        :: "r"((uint32_t)(sma)), "r"((uint32_t)(n)) : "memory")
#define TCGEN05_DEALLOC(tm, n) \
    asm volatile("tcgen05.dealloc.cta_group::1.sync.aligned.b32 %0, %1;" :: "r"(tm), "r"((uint32_t)(n)))
#define TCGEN05_RELINQ() \
    asm volatile("tcgen05.relinquish_alloc_permit.cta_group::1.sync.aligned;")
#define TCGEN05_COMMIT(mb) \
    asm volatile("tcgen05.commit.cta_group::1.mbarrier::arrive::one.shared::cluster.b64 [%0];" \
        :: "r"((uint32_t)(mb)) : "memory")
#define TCGEN05_FENCE_BEFORE() asm volatile("tcgen05.fence::before_thread_sync;" ::: "memory")
#define TCGEN05_FENCE_AFTER()  asm volatile("tcgen05.fence::after_thread_sync;" ::: "memory")
#define TCGEN05_WAIT_LD()      asm volatile("tcgen05.wait::ld.sync.aligned;" ::: "memory")
#define FENCE_PROXY_ASYNC()    asm volatile("fence.proxy.async.shared::cta;" ::: "memory")
#define TCGEN05_LD_X32(r, tma) \
    asm volatile("tcgen05.ld.sync.aligned.32x32b.x32.b32 " \
        "{%0,%1,%2,%3,%4,%5,%6,%7,%8,%9,%10,%11,%12,%13,%14,%15," \
        "%16,%17,%18,%19,%20,%21,%22,%23,%24,%25,%26,%27,%28,%29,%30,%31}, [%32];" \
        : "=r"((r)[0]), "=r"((r)[1]), "=r"((r)[2]), "=r"((r)[3]),   \
          "=r"((r)[4]), "=r"((r)[5]), "=r"((r)[6]), "=r"((r)[7]),   \
          "=r"((r)[8]), "=r"((r)[9]), "=r"((r)[10]), "=r"((r)[11]), \
          "=r"((r)[12]), "=r"((r)[13]), "=r"((r)[14]), "=r"((r)[15]), \
          "=r"((r)[16]), "=r"((r)[17]), "=r"((r)[18]), "=r"((r)[19]), \
          "=r"((r)[20]), "=r"((r)[21]), "=r"((r)[22]), "=r"((r)[23]), \
          "=r"((r)[24]), "=r"((r)[25]), "=r"((r)[26]), "=r"((r)[27]), \
          "=r"((r)[28]), "=r"((r)[29]), "=r"((r)[30]), "=r"((r)[31]) \
        : "r"(tma))
static constexpr uint64_t SMEM_DESC_BASE_SW128 =
    (uint64_t(2) << 61) | (uint64_t(1) << 46) | (uint64_t(64) << 32) | (uint64_t(1) << 16);
#define MAKE_SMEM_DESC(ba) (SMEM_DESC_BASE_SW128 | ((uint64_t)((ba) >> 4) & 0x3FFF))
__device__ __forceinline__ void bulk_g2s(uint32_t dst, const void* src, uint32_t bytes, uint32_t mbar) {
    asm volatile("cp.async.bulk.shared::cluster.global.mbarrier::complete_tx::bytes [%0], [%1], %2, [%3];"
        :: "r"(dst), "l"(src), "r"(bytes), "r"(mbar) : "memory");
}
__device__ __forceinline__ void mma_f16_ss(uint32_t d, uint64_t ad, uint64_t bd, uint32_t idesc, bool en) {
    uint32_t e = en ? 1u : 0u;
    asm volatile("{\n\t.reg .pred p;\n\tsetp.ne.u32 p, %5, 0;\n\t"
        "tcgen05.mma.cta_group::1.kind::f16 [%0], %1, %2, %3, {%4, %4, %4, %4}, p;\n\t}"
        :: "r"(d), "l"(ad), "l"(bd), "r"(idesc), "r"(0u), "r"(e) : "memory");
}
#define ID_BF  ((1u << 4) | (1u << 7) | (1u << 10) | (16u << 17) | (8u << 24))
#define ID_F16 ((1u << 4) | (16u << 17) | (8u << 24))
#endif

// ---------------- producers (unchanged, passing) ----------------
__global__ void quant_x_kernel(const float* __restrict__ hs) {
    int t = blockIdx.x * blockDim.x + threadIdx.x;
    if (t >= S_LEN * D_DIM / 8) return;
    int idx = t * 8;
    int s = idx >> 12, d = idx & (D_DIM - 1);
    float4 v0 = *(const float4*)(hs + idx);
    float4 v1 = *(const float4*)(hs + idx + 4);
    int q0 = clampi(__float2int_rn(__fdiv_rn(v0.x, 0.1f)), -128, 127);
    int q1 = clampi(__float2int_rn(__fdiv_rn(v0.y, 0.1f)), -128, 127);
    int q2 = clampi(__float2int_rn(__fdiv_rn(v0.z, 0.1f)), -128, 127);
    int q3 = clampi(__float2int_rn(__fdiv_rn(v0.w, 0.1f)), -128, 127);
    int q4 = clampi(__float2int_rn(__fdiv_rn(v1.x, 0.1f)), -128, 127);
    int q5 = clampi(__float2int_rn(__fdiv_rn(v1.y, 0.1f)), -128, 127);
    int q6 = clampi(__float2int_rn(__fdiv_rn(v1.z, 0.1f)), -128, 127);
    int q7 = clampi(__float2int_rn(__fdiv_rn(v1.w, 0.1f)), -128, 127);
    int mt = s >> 7, r = s & 127, kt = d >> 6, c = d & 63;
    *(uint4*)((char*)g_xa + (((size_t)(mt * 64 + kt)) << 14) + sw_off(r, c)) =
        make_uint4(bfpack(q0, q1), bfpack(q2, q3), bfpack(q4, q5), bfpack(q6, q7));
}

__global__ void convert_w_kernel(const float* __restrict__ wq, const float* __restrict__ wk,
                                 const float* __restrict__ wv, const float* __restrict__ wo) {
    int t = blockIdx.x * blockDim.x + threadIdx.x;
    int z = blockIdx.y;
    if (t >= D_DIM * D_DIM / 8) return;
    const float* src = (z == 0) ? wq : (z == 1) ? wk : (z == 2) ? wv : wo;
    int idx = t * 8;
    int o = idx >> 12, k = idx & (D_DIM - 1);
    float4 v0 = *(const float4*)(src + idx);
    float4 v1 = *(const float4*)(src + idx + 4);
    int q0 = __float2int_rn(v0.x), q1 = __float2int_rn(v0.y);
    int q2 = __float2int_rn(v0.z), q3 = __float2int_rn(v0.w);
    int q4 = __float2int_rn(v1.x), q5 = __float2int_rn(v1.y);
    int q6 = __float2int_rn(v1.z), q7 = __float2int_rn(v1.w);
    int nt = o >> 7, r = o & 127, kt = k >> 6, c = k & 63;
    *(uint4*)((char*)g_wb[z] + (((size_t)(nt * 64 + kt)) << 14) + sw_off(r, c)) =
        make_uint4(bfpack(q0, q1), bfpack(q2, q3), bfpack(q4, q5), bfpack(q6, q7));
}

__global__ void rope_table_kernel(const int* __restrict__ pos) {
    int idx = blockIdx.x * blockDim.x + threadIdx.x;
    if (idx >= S_LEN * 64) return;
    int s = idx >> 6, i = idx & 63;
    float e = (float)(2 * i) * (1.0f / 128.0f);
    float powf32 = (float)pow(10000.0, (double)e);
    float invf = 1.0f / powf32;
    float ang = (float)pos[s] * invf;
    double a = (double)ang;
    g_rope[idx] = make_float2((float)cos(a), (float)sin(a));
}

__global__ void ropequant_qk_kernel(const float* __restrict__ sq, const float* __restrict__ sk) {
    int idx = blockIdx.x * blockDim.x + threadIdx.x;
    if (idx >= S_LEN * D_DIM) return;
    int s = idx >> 12, o = idx & (D_DIM - 1);
    int h = o >> 7, j = o & 127;
    float2 cs = g_rope[(s << 6) + (j & 63)];
    int o2 = (h << 7) + ((j < 64) ? (j + 64) : (j - 64));
    float sign = (j < 64) ? -1.0f : 1.0f;
    int base = s * D_DIM;
    size_t tile = ((size_t)(h * 16 + (s >> 7))) << 15;
    uint32_t off = ((uint32_t)(j >> 6) << 14) + sw_off(s & 127, j & 63);
    {
        float a = __fmul_rn((float)g_pint[0][base + o],  __fmul_rn(0.1f, sq[o]));
        float b = __fmul_rn((float)g_pint[0][base + o2], __fmul_rn(0.1f, sq[o2])) * sign;
        float r = __fadd_rn(__fmul_rn(a, cs.x), __fmul_rn(b, cs.y));
        int q = clampi(__float2int_rn(__fdiv_rn(r, 0.1f)), -128, 127);
        *(__nv_bfloat16*)((char*)g_qb + tile + off) = __float2bfloat16_rn((float)q);
    }
    {
        float a = __fmul_rn((float)g_pint[1][base + o],  __fmul_rn(0.1f, sk[o]));
        float b = __fmul_rn((float)g_pint[1][base + o2], __fmul_rn(0.1f, sk[o2])) * sign;
        float r = __fadd_rn(__fmul_rn(a, cs.x), __fmul_rn(b, cs.y));
        int q = clampi(__float2int_rn(__fdiv_rn(r, 0.1f)), -128, 127);
        *(__nv_bfloat16*)((char*)g_kb + tile + off) = __float2bfloat16_rn((float)q);
    }
}

__global__ void transpose_v_kernel(const float* __restrict__ sv) {
    __shared__ __half ts[32][136];
    int h = blockIdx.z, j0 = blockIdx.y * 32;
    int tid = threadIdx.x;
    int tx = tid & 31, ty = tid >> 5;
    int j = j0 + tx;
    float sc = __fmul_rn(0.1f, sv[h * 128 + j]);
    int s0 = blockIdx.x * 128;
    #pragma unroll
    for (int si = ty; si < 128; si += 8) {
        float a = __fmul_rn((float)g_pint[2][(s0 + si) * D_DIM + h * 128 + j], sc);
        int q = clampi(__float2int_rn(__fdiv_rn(a, 0.1f)), -128, 127);
        ts[tx][si] = __float2half_rn((float)q);
    }
    __syncthreads();
    char* base = (char*)g_vt + (((size_t)(h * 16 + blockIdx.x)) << 15);
    for (int e = tid; e < 32 * 16; e += 256) {
        int jj = e >> 4, sb = (e & 15) * 8;
        int d = j0 + jj;
        uint4 v;
        __half* hp = (__half*)&v;
        #pragma unroll
        for (int u = 0; u < 8; u++) hp[u] = ts[jj][sb + u];
        *(uint4*)(base + ((sb >> 6) << 14) + (uint32_t)((d * 128 + (sb & 63) * 2) ^ ((d & 7) << 4))) = v;
    }
}

// ---------------- tcgen05 GEMM (unchanged, passing) ----------------
#define NST 3
#define STG_B 65536
#define T_OFF_BAR 16
#define T_OFF_DONE 80
#define T_OFF_ST 1024
#define SMEM_TC (T_OFF_ST + NST * STG_B)

__global__ __launch_bounds__(128, 1) __cluster_dims__(1, 1, 1)
void gemm_tc_kernel(int mode, const float* __restrict__ so, float* __restrict__ out) {
#if USE_TC
    extern __shared__ __align__(1024) char sm[];
    uint32_t sb = smem_u32(sm);
    int tid = threadIdx.x, wid = tid >> 5, lid = tid & 31;
    const char* A; const char* B; int* C;
    if (mode == 0) { A = (const char*)g_xa; B = (const char*)g_wb[blockIdx.z]; C = g_pint[blockIdx.z]; }
    else           { A = (const char*)g_oa; B = (const char*)g_wb[3];          C = g_pint[0]; }
    int my = blockIdx.y, nt = blockIdx.x;
    if (wid == 0) { TCGEN05_ALLOC(sb, 512); TCGEN05_RELINQ(); }
    if (tid == 0) {
        #pragma unroll
        for (int s = 0; s < NST; s++) {
            MBARRIER_INIT(sb + T_OFF_BAR + s * 16, 1);
            MBARRIER_INIT(sb + T_OFF_BAR + s * 16 + 8, 1);
        }
        MBARRIER_INIT(sb + T_OFF_DONE, 1);
    }
    __syncthreads();
    uint32_t tmem;
    asm volatile("ld.shared.b32 %0, [%1];" : "=r"(tmem) : "r"(sb));
    const int KT = KDIM / 64;
    if (tid == 0) {
        for (int kt = 0; kt < KT; kt++) {
            int st = kt % NST, it = kt / NST;
            uint32_t fullb = sb + T_OFF_BAR + st * 16, emptyb = fullb + 8;
            if (kt >= NST) MBARRIER_WAIT_PARITY(emptyb, (it - 1) & 1);
            MBARRIER_EXPECT_TX(fullb, STG_B);
            uint32_t dst = sb + T_OFF_ST + st * STG_B;
            bulk_g2s(dst,         A + ((size_t)((2 * my)     * 64 + kt) << 14), 16384, fullb);
            bulk_g2s(dst + 16384, A + ((size_t)((2 * my + 1) * 64 + kt) << 14), 16384, fullb);
            bulk_g2s(dst + 32768, B + ((size_t)((2 * nt)     * 64 + kt) << 14), 16384, fullb);
            bulk_g2s(dst + 49152, B + ((size_t)((2 * nt + 1) * 64 + kt) << 14), 16384, fullb);
        }
    } else if (tid == 32) {
        for (int kt = 0; kt < KT; kt++) {
            int st = kt % NST, it = kt / NST;
            uint32_t fullb = sb + T_OFF_BAR + st * 16, emptyb = fullb + 8;
            MBARRIER_WAIT_PARITY(fullb, it & 1);
            uint32_t base = sb + T_OFF_ST + st * STG_B;
            uint64_t a0 = MAKE_SMEM_DESC(base);
            uint64_t a1 = MAKE_SMEM_DESC(base + 16384);
            uint64_t b0 = MAKE_SMEM_DESC(base + 32768);
            uint64_t b1 = MAKE_SMEM_DESC(base + 49152);
            #pragma unroll
            for (int sub = 0; sub < 4; sub++) {
                bool en = (kt > 0) || (sub > 0);
                mma_f16_ss(tmem,       a0 + sub * 2, b0 + sub * 2, ID_BF, en);
                mma_f16_ss(tmem + 128, a0 + sub * 2, b1 + sub * 2, ID_BF, en);
                mma_f16_ss(tmem + 256, a1 + sub * 2, b0 + sub * 2, ID_BF, en);
                mma_f16_ss(tmem + 384, a1 + sub * 2, b1 + sub * 2, ID_BF, en);
            }
            TCGEN05_COMMIT(emptyb);
        }
        TCGEN05_COMMIT(sb + T_OFF_DONE);
    }
    MBARRIER_WAIT_PARITY(sb + T_OFF_DONE, 0);
    TCGEN05_FENCE_AFTER();
    #pragma unroll
    for (int half = 0; half < 2; half++) {
        int mrow = my * 256 + half * 128 + wid * 32 + lid;
        #pragma unroll
        for (int hh = 0; hh < 2; hh++) {
            uint32_t tb = tmem + half * 256 + hh * 128;
            #pragma unroll
            for (int c0 = 0; c0 < 128; c0 += 32) {
                uint32_t r[32];
                TCGEN05_LD_X32(r, tb + c0);
                TCGEN05_WAIT_LD();
                if (mode == 0) {
                    int* Crow = C + (size_t)mrow * D_DIM + nt * 256 + hh * 128;
                    #pragma unroll
                    for (int j = 0; j < 32; j += 4)
                        *(int4*)(Crow + c0 + j) = make_int4(
                            __float2int_rn(__uint_as_float(r[j])), __float2int_rn(__uint_as_float(r[j + 1])),
                            __float2int_rn(__uint_as_float(r[j + 2])), __float2int_rn(__uint_as_float(r[j + 3])));
                } else {
                    float* Orow = out + (size_t)mrow * D_DIM + nt * 256 + hh * 128;
                    #pragma unroll
                    for (int j = 0; j < 32; j++)
                        Orow[c0 + j] = __fmul_rn(__uint_as_float(r[j]),
                                                 __fmul_rn(0.1f, so[nt * 256 + hh * 128 + c0 + j]));
                }
            }
        }
    }
    __syncthreads();
    if (wid == 0) TCGEN05_DEALLOC(tmem, 512);
#endif
}

// ---------------- tcgen05 flash attention: S ping-pong + fused FFMA/EX2 softmax ----------------
#define A_Q 3072
#define A_K (A_Q + 32768)
#define A_V (A_K + 65536)
#define A_P (A_V + 65536)
#define SMEM_ATT (A_P + 65536)   // 232448

__global__ __launch_bounds__(256, 1) __cluster_dims__(1, 1, 1) void attn_kernel() {
#if USE_TC
    extern __shared__ __align__(1024) char sm[];
    uint32_t sb = smem_u32(sm);
    int qt = (int)gridDim.x - 1 - (int)blockIdx.x;
    int h = blockIdx.y;
    int tid = threadIdx.x, wid = tid >> 5, ln = tid & 31;
    int row = ((wid & 3) << 5) + ln;
    int ch = wid >> 2;
    uint32_t cbase = (uint32_t)ch * 64;
    float* red = (float*)(sm + A_P);
    const double SCd = (double)0.1f * (double)0.1f / 11.313708498984760390;
    const float C1 = (float)(SCd * 1.4426950408889634074);   // SC*log2(e)

    if (wid == 0) { TCGEN05_ALLOC(sb, 512); TCGEN05_RELINQ(); }
    if (tid == 0) { MBARRIER_INIT(sb + 16, 1); MBARRIER_INIT(sb + 24, 1); }
    __syncthreads();
    uint32_t tmem;
    asm volatile("ld.shared.b32 %0, [%1];" : "=r"(tmem) : "r"(sb));
    uint32_t tO = tmem + 128;   // S regions: tmem+0 (even kt), tmem+256 (odd kt)

    const char* Kg = (const char*)g_kb + (((size_t)(h * 16)) << 15);
    const char* Vg = (const char*)g_vt + (((size_t)(h * 16)) << 15);
    uint64_t qd = MAKE_SMEM_DESC(sb + A_Q);
    int nS = 0;

    // ===== pass A: exact row max =====
    {
        const char* Qg = (const char*)g_qb + (((size_t)(h * 16 + qt)) << 15);
        for (int i = tid; i < 2048; i += 256) cp_async16(sm + A_Q + i * 16, Qg + i * 16);
        for (int i = tid; i < 2048; i += 256) cp_async16(sm + A_K + i * 16, Kg + i * 16);
        cp_commit();
        const char* K1 = Kg + (((size_t)min(1, 15)) << 15);
        for (int i = tid; i < 2048; i += 256) cp_async16(sm + A_K + 32768 + i * 16, K1 + i * 16);
        cp_commit();
        asm volatile("cp.async.wait_group 0;\n");   // Q, K0, K1 resident
        __syncthreads();
        if (tid == 0) {
            uint64_t kd = MAKE_SMEM_DESC(sb + A_K);
            #pragma unroll
            for (int kc = 0; kc < 2; kc++)
                #pragma unroll
                for (int s2 = 0; s2 < 4; s2++)
                    mma_f16_ss(tmem, qd + kc * 1024 + s2 * 2, kd + kc * 1024 + s2 * 2, ID_BF, (kc | s2) != 0);
            TCGEN05_COMMIT(sb + 16);
        }
    }
    float Mf = -1e30f;
    for (int kt = 0; kt <= qt; kt++) {
        MBARRIER_WAIT_PARITY(sb + 16, nS & 1); nS++;    // S(kt) done
        TCGEN05_FENCE_AFTER();
        uint32_t tSc = tmem + ((kt & 1) ? 256u : 0u);
        if (tid == 0 && kt < qt) {                      // issue S(kt+1) into other region (K(kt+1) resident)
            uint32_t tSn = tmem + (((kt + 1) & 1) ? 256u : 0u);
            uint64_t kd = MAKE_SMEM_DESC(sb + A_K + ((kt + 1) & 1) * 32768);
            #pragma unroll
            for (int kc = 0; kc < 2; kc++)
                #pragma unroll
                for (int s2 = 0; s2 < 4; s2++)
                    mma_f16_ss(tSn, qd + kc * 1024 + s2 * 2, kd + kc * 1024 + s2 * 2, ID_BF, (kc | s2) != 0);
            TCGEN05_COMMIT(sb + 16);
        }
        if (kt < qt) {                                  // stage K(kt+2) into buf kt&1 (K(kt) consumed)
            const char* src = Kg + (((size_t)min(kt + 2, 15)) << 15);
            char* dst = sm + A_K + (kt & 1) * 32768;
            for (int i = tid; i < 2048; i += 256) cp_async16(dst + i * 16, src + i * 16);
            cp_commit();
        }
        uint32_t r0[32], r1[32];
        TCGEN05_LD_X32(r0, tSc + cbase);
        TCGEN05_LD_X32(r1, tSc + cbase + 32);
        TCGEN05_WAIT_LD();
        TCGEN05_FENCE_BEFORE();
        bool diag = (kt == qt);
        #pragma unroll
        for (int j = 0; j < 32; j++) {
            float v0 = __uint_as_float(r0[j]), v1 = __uint_as_float(r1[j]);
            if (!diag || (int)(cbase + j) <= row)      Mf = fmaxf(Mf, v0);
            if (!diag || (int)(cbase + 32 + j) <= row) Mf = fmaxf(Mf, v1);
        }
        asm volatile("cp.async.wait_group 0;\n");       // K(kt+2) resident for next iter's issue
        __syncthreads();                                // tS region reads done before reuse
    }
    red[(ch << 7) + row] = Mf;
    __syncthreads();
    Mf = fmaxf(red[row], red[128 + row]);
    __syncthreads();
    const float c2 = __fmul_rn(-Mf, C1);
    float l = 0.0f;

    // ===== pass B =====
    for (int i = tid; i < 2048; i += 256) cp_async16(sm + A_K + i * 16, Kg + i * 16);
    for (int i = tid; i < 2048; i += 256) cp_async16(sm + A_V + i * 16, Vg + i * 16);
    cp_commit();
    {
        const char* K1 = Kg + (((size_t)min(1, 15)) << 15);
        for (int i = tid; i < 2048; i += 256) cp_async16(sm + A_K + 32768 + i * 16, K1 + i * 16);
        cp_commit();
    }
    asm volatile("cp.async.wait_group 0;\n");
    __syncthreads();
    if (tid == 0) {
        uint64_t kd = MAKE_SMEM_DESC(sb + A_K);
        #pragma unroll
        for (int kc = 0; kc < 2; kc++)
            #pragma unroll
            for (int s2 = 0; s2 < 4; s2++)
                mma_f16_ss(tmem, qd + kc * 1024 + s2 * 2, kd + kc * 1024 + s2 * 2, ID_BF, (kc | s2) != 0);
        TCGEN05_COMMIT(sb + 16);
    }
    uint64_t pd = MAKE_SMEM_DESC(sb + A_P);
    uint64_t pld = MAKE_SMEM_DESC(sb + A_P + 32768);

    for (int kt = 0; kt <= qt; kt++) {
        MBARRIER_WAIT_PARITY(sb + 16, nS & 1); nS++;    // S(kt) done
        TCGEN05_FENCE_AFTER();
        uint32_t tSc = tmem + ((kt & 1) ? 256u : 0u);
        if (tid == 0 && kt < qt) {                      // issue S(kt+1) immediately (ping-pong region)
            uint32_t tSn = tmem + (((kt + 1) & 1) ? 256u : 0u);
            uint64_t kd = MAKE_SMEM_DESC(sb + A_K + ((kt + 1) & 1) * 32768);
            #pragma unroll
            for (int kc = 0; kc < 2; kc++)
                #pragma unroll
                for (int s2 = 0; s2 < 4; s2++)
                    mma_f16_ss(tSn, qd + kc * 1024 + s2 * 2, kd + kc * 1024 + s2 * 2, ID_BF, (kc | s2) != 0);
            TCGEN05_COMMIT(sb + 16);
        }
        if (kt < qt) {                                  // K(kt+2) as its own cp group (drained before next S issue)
            const char* ks = Kg + (((size_t)min(kt + 2, 15)) << 15);
            char* kd2 = sm + A_K + (kt & 1) * 32768;
            for (int i = tid; i < 2048; i += 256) cp_async16(kd2 + i * 16, ks + i * 16);
            cp_commit();
        }
        uint32_t r0[32], r1[32];
        TCGEN05_LD_X32(r0, tSc + cbase);
        TCGEN05_LD_X32(r1, tSc + cbase + 32);
        TCGEN05_WAIT_LD();
        TCGEN05_FENCE_BEFORE();
        // softmax: p = ex2(fma(s, C1, c2))  (overlaps S(kt+1) MMA)
        bool diag = (kt == qt);
        uint32_t ph[2][16], pl[2][16];
        #pragma unroll
        for (int b = 0; b < 2; b++) {
            const uint32_t* rr = (b == 0) ? r0 : r1;
            #pragma unroll
            for (int jj = 0; jj < 16; jj++) {
                int c = (int)cbase + b * 32 + 2 * jj;
                float p0 = 0.0f, p1 = 0.0f;
                if (!diag || c <= row)     p0 = ex2f(fmaf(__uint_as_float(rr[2 * jj]),     C1, c2));
                if (!diag || c + 1 <= row) p1 = ex2f(fmaf(__uint_as_float(rr[2 * jj + 1]), C1, c2));
                l += p0 + p1;
                splitpk2(p0, p1, ph[b][jj], pl[b][jj]);
            }
        }
        if (kt > 0) { MBARRIER_WAIT_PARITY(sb + 24, (kt - 1) & 1); TCGEN05_FENCE_AFTER(); }  // frees P, V(kt-1)
        #pragma unroll
        for (int b = 0; b < 2; b++)
            #pragma unroll
            for (int g = 0; g < 4; g++) {
                uint32_t so2 = ((uint32_t)ch << 14) + sw_off(row, b * 32 + g * 8);
                *(uint4*)(sm + A_P + so2) =
                    make_uint4(ph[b][4 * g], ph[b][4 * g + 1], ph[b][4 * g + 2], ph[b][4 * g + 3]);
                *(uint4*)(sm + A_P + 32768 + so2) =
                    make_uint4(pl[b][4 * g], pl[b][4 * g + 1], pl[b][4 * g + 2], pl[b][4 * g + 3]);
            }
        FENCE_PROXY_ASYNC();
        if (kt < qt) {                                  // V(kt+1) own group; wait 1 drains K-grp + older
            const char* vs = Vg + (((size_t)(kt + 1)) << 15);
            char* vd2 = sm + A_V + ((kt + 1) & 1) * 32768;
            for (int i = tid; i < 2048; i += 256) cp_async16(vd2 + i * 16, vs + i * 16);
            cp_commit();
            asm volatile("cp.async.wait_group 1;\n");
        } else {
            asm volatile("cp.async.wait_group 0;\n");
        }
        __syncthreads();
        if (tid == 0) {
            uint64_t vd = MAKE_SMEM_DESC(sb + A_V + (kt & 1) * 32768);
            #pragma unroll
            for (int kc = 0; kc < 2; kc++)
                #pragma unroll
                for (int s2 = 0; s2 < 4; s2++) {
                    bool en = (kt > 0) || (kc | s2) != 0;
                    mma_f16_ss(tO, pd  + kc * 1024 + s2 * 2, vd + kc * 1024 + s2 * 2, ID_F16, en);
                    mma_f16_ss(tO, pld + kc * 1024 + s2 * 2, vd + kc * 1024 + s2 * 2, ID_F16, true);
                }
            TCGEN05_COMMIT(sb + 24);
        }
    }
    MBARRIER_WAIT_PARITY(sb + 24, qt & 1);
    TCGEN05_FENCE_AFTER();

    red[(ch << 7) + row] = l;
    __syncthreads();
    float lsum = red[row] + red[128 + row];

    int sg = qt * 128 + row;
    #pragma unroll
    for (int b = 0; b < 2; b++) {
        uint32_t r[32];
        TCGEN05_LD_X32(r, tO + cbase + b * 32);
        TCGEN05_WAIT_LD();
        #pragma unroll
        for (int jj = 0; jj < 16; jj++) {
            float x0 = __fmul_rn(__fdiv_rn(__uint_as_float(r[2 * jj]), lsum), 0.1f);
            float x1 = __fmul_rn(__fdiv_rn(__uint_as_float(r[2 * jj + 1]), lsum), 0.1f);
            int q0 = clampi(__float2int_rn(__fdiv_rn(x0, 0.1f)), -127, 127);
            int q1 = clampi(__float2int_rn(__fdiv_rn(x1, 0.1f)), -127, 127);
            int col = h * 128 + (int)cbase + b * 32 + 2 * jj;
            *(uint32_t*)((char*)g_oa + (((size_t)((sg >> 7) * 64 + (col >> 6))) << 14) + sw_off(sg & 127, col & 63)) =
                bfpack(q0, q1);
        }
    }
    __syncthreads();
    if (wid == 0) TCGEN05_DEALLOC(tmem, 512);
#endif
}

// ---------------- launch ----------------
extern "C" void kernel_launch(void* const* d_in, const int* in_sizes, int n_in,
                              void* d_out, int out_size) {
    const float* hs = (const float*)d_in[0];
    const float* wq = (const float*)d_in[1];
    const float* wk = (const float*)d_in[2];
    const float* wv = (const float*)d_in[3];
    const float* wo = (const float*)d_in[4];
    const float* sq = (const float*)d_in[5];
    const float* sk = (const float*)d_in[6];
    const float* sv = (const float*)d_in[7];
    const float* so = (const float*)d_in[8];
    const int*   pos = (const int*)d_in[10];
    float* out = (float*)d_out;

    cudaFuncSetAttribute(gemm_tc_kernel, cudaFuncAttributeMaxDynamicSharedMemorySize, SMEM_TC);
    cudaFuncSetAttribute(attn_kernel, cudaFuncAttributeMaxDynamicSharedMemorySize, SMEM_ATT);

    quant_x_kernel<<<(S_LEN * D_DIM / 8 + 255) / 256, 256>>>(hs);
    convert_w_kernel<<<dim3((D_DIM * D_DIM / 8 + 255) / 256, 4), 256>>>(wq, wk, wv, wo);
    rope_table_kernel<<<(S_LEN * 64 + 255) / 256, 256>>>(pos);

    gemm_tc_kernel<<<dim3(D_DIM / 256, S_LEN / 256, 3), 128, SMEM_TC>>>(0, so, out);   // QKV

    ropequant_qk_kernel<<<(S_LEN * D_DIM + 255) / 256, 256>>>(sq, sk);
    transpose_v_kernel<<<dim3(S_LEN / 128, 4, H_NUM), 256>>>(sv);

    attn_kernel<<<dim3(S_LEN / 128, H_NUM), 256, SMEM_ATT>>>();

    gemm_tc_kernel<<<dim3(D_DIM / 256, S_LEN / 256, 1), 128, SMEM_TC>>>(1, so, out);   // o-proj
}

// round 17
// speedup vs baseline: 1.4712x; 1.4712x over previous
#include <cuda_runtime.h>
#include <cuda_fp16.h>
#include <cuda_bf16.h>
#include <math.h>
#include <stdint.h>

#define S_LEN 2048
#define D_DIM 4096
#define H_NUM 32
#define HD    128
#define KDIM  4096

#if defined(__CUDA_ARCH__) && (defined(__CUDA_ARCH_FEAT_SM103_ALL) || defined(__CUDA_ARCH_FEAT_SM100_ALL) || defined(__CUDA_ARCH_SPECIFIC__) || defined(__CUDA_ARCH_FAMILY_SPECIFIC__))
#define USE_TC 1
#else
#define USE_TC 0
#endif

__device__ __nv_bfloat16 g_xa[S_LEN * D_DIM];
__device__ __nv_bfloat16 g_wb[4][D_DIM * D_DIM];
__device__ __nv_bfloat16 g_oa[S_LEN * D_DIM];
__device__ int    g_pint[3][S_LEN * D_DIM];
__device__ __nv_bfloat16 g_qb[H_NUM * S_LEN * HD];  // Q bf16 tiled [h*16+qt][32KB SW128]
__device__ __nv_bfloat16 g_kb[H_NUM * S_LEN * HD];  // K bf16 tiled
__device__ __half        g_vt[H_NUM * S_LEN * HD];  // V^T fp16 tiled [h*16+st][rows=d][cols=s]
__device__ float2 g_rope[S_LEN * 64];

__device__ __forceinline__ void cp_async16(void* smem, const void* gmem) {
    unsigned saddr = (unsigned)__cvta_generic_to_shared(smem);
    asm volatile("cp.async.cg.shared.global [%0], [%1], 16;\n" :: "r"(saddr), "l"(gmem));
}
__device__ __forceinline__ void cp_commit() { asm volatile("cp.async.commit_group;\n"); }
__device__ __forceinline__ int clampi(int v, int lo, int hi) { return max(lo, min(hi, v)); }
__device__ __forceinline__ uint32_t sw_off(int r, int c) {
    return (uint32_t)((r * 128 + c * 2) ^ ((r & 7) << 4));
}
__device__ __forceinline__ void splitpk2(float x0, float x1, uint32_t& hi, uint32_t& lo) {
    __half2 h = __floats2half2_rn(x0, x1);
    float2 f = __half22float2(h);
    __half2 e = __floats2half2_rn(x0 - f.x, x1 - f.y);
    hi = *(uint32_t*)&h;
    lo = *(uint32_t*)&e;
}
__device__ __forceinline__ uint32_t bfpack(int a, int b) {
    return (uint32_t)__bfloat16_as_ushort(__float2bfloat16_rn((float)a)) |
           ((uint32_t)__bfloat16_as_ushort(__float2bfloat16_rn((float)b)) << 16);
}
__device__ __forceinline__ float ex2f(float x) {
    float r;
    asm("ex2.approx.f32 %0, %1;" : "=f"(r) : "f"(x));
    return r;
}

#if USE_TC
__device__ __forceinline__ uint32_t smem_u32(const void* p) {
    uint32_t a;
    asm("{ .reg .u64 t; cvta.to.shared.u64 t, %1; cvt.u32.u64 %0, t; }" : "=r"(a) : "l"(p));
    return a;
}
#define MBARRIER_INIT(addr, cnt) \
    asm volatile("mbarrier.init.shared.b64 [%0], %1;" :: "r"((uint32_t)(addr)), "r"((uint32_t)(cnt)) : "memory")
#define MBARRIER_WAIT_PARITY(addr, ph) do {                                   \
    uint32_t _m = (uint32_t)(addr); uint32_t _p = (uint32_t)(ph);             \
    asm volatile("{\n\t.reg .pred P1;\n\t"                                    \
        "WL_%=:\n\t"                                                          \
        "mbarrier.try_wait.parity.acquire.cta.shared::cta.b64 P1, [%0], %1, 0x989680;\n\t" \
        "@P1 bra.uni WD_%=;\n\t"                                              \
        "bra.uni WL_%=;\n\t"                                                  \
        "WD_%=:\n\t}"                                                         \
        :: "r"(_m), "r"(_p) : "memory");                                      \
} while (0)
#define MBARRIER_EXPECT_TX(addr, bytes) \
    asm volatile("mbarrier.arrive.expect_tx.shared.b64 _, [%0], %1;" :: "r"((uint32_t)(addr)), "r"((uint32_t)(bytes)) : "memory")
#define TCGEN05_ALLOC(sma, n) \
    asm volatile("tcgen05.alloc.cta_group::1.sync.aligned.shared::cta.b32 [%0], %1;" \
        :: "r"((uint32_t)(sma)), "r"((uint32_t)(n)) : "memory")
#define TCGEN05_DEALLOC(tm, n) \
    asm volatile("tcgen05.dealloc.cta_group::1.sync.aligned.b32 %0, %1;" :: "r"(tm), "r"((uint32_t)(n)))
#define TCGEN05_RELINQ() \
    asm volatile("tcgen05.relinquish_alloc_permit.cta_group::1.sync.aligned;")
#define TCGEN05_COMMIT(mb) \
    asm volatile("tcgen05.commit.cta_group::1.mbarrier::arrive::one.shared::cluster.b64 [%0];" \
        :: "r"((uint32_t)(mb)) : "memory")
#define TCGEN05_FENCE_BEFORE() asm volatile("tcgen05.fence::before_thread_sync;" ::: "memory")
#define TCGEN05_FENCE_AFTER()  asm volatile("tcgen05.fence::after_thread_sync;" ::: "memory")
#define TCGEN05_WAIT_LD()      asm volatile("tcgen05.wait::ld.sync.aligned;" ::: "memory")
#define FENCE_PROXY_ASYNC()    asm volatile("fence.proxy.async.shared::cta;" ::: "memory")
#define TCGEN05_LD_X32(r, tma) \
    asm volatile("tcgen05.ld.sync.aligned.32x32b.x32.b32 " \
        "{%0,%1,%2,%3,%4,%5,%6,%7,%8,%9,%10,%11,%12,%13,%14,%15," \
        "%16,%17,%18,%19,%20,%21,%22,%23,%24,%25,%26,%27,%28,%29,%30,%31}, [%32];" \
        : "=r"((r)[0]), "=r"((r)[1]), "=r"((r)[2]), "=r"((r)[3]),   \
          "=r"((r)[4]), "=r"((r)[5]), "=r"((r)[6]), "=r"((r)[7]),   \
          "=r"((r)[8]), "=r"((r)[9]), "=r"((r)[10]), "=r"((r)[11]), \
          "=r"((r)[12]), "=r"((r)[13]), "=r"((r)[14]), "=r"((r)[15]), \
          "=r"((r)[16]), "=r"((r)[17]), "=r"((r)[18]), "=r"((r)[19]), \
          "=r"((r)[20]), "=r"((r)[21]), "=r"((r)[22]), "=r"((r)[23]), \
          "=r"((r)[24]), "=r"((r)[25]), "=r"((r)[26]), "=r"((r)[27]), \
          "=r"((r)[28]), "=r"((r)[29]), "=r"((r)[30]), "=r"((r)[31]) \
        : "r"(tma))
static constexpr uint64_t SMEM_DESC_BASE_SW128 =
    (uint64_t(2) << 61) | (uint64_t(1) << 46) | (uint64_t(64) << 32) | (uint64_t(1) << 16);
#define MAKE_SMEM_DESC(ba) (SMEM_DESC_BASE_SW128 | ((uint64_t)((ba) >> 4) & 0x3FFF))
__device__ __forceinline__ void bulk_g2s(uint32_t dst, const void* src, uint32_t bytes, uint32_t mbar) {
    asm volatile("cp.async.bulk.shared::cluster.global.mbarrier::complete_tx::bytes [%0], [%1], %2, [%3];"
        :: "r"(dst), "l"(src), "r"(bytes), "r"(mbar) : "memory");
}
__device__ __forceinline__ void mma_f16_ss(uint32_t d, uint64_t ad, uint64_t bd, uint32_t idesc, bool en) {
    uint32_t e = en ? 1u : 0u;
    asm volatile("{\n\t.reg .pred p;\n\tsetp.ne.u32 p, %5, 0;\n\t"
        "tcgen05.mma.cta_group::1.kind::f16 [%0], %1, %2, %3, {%4, %4, %4, %4}, p;\n\t}"
        :: "r"(d), "l"(ad), "l"(bd), "r"(idesc), "r"(0u), "r"(e) : "memory");
}
#define ID_BF  ((1u << 4) | (1u << 7) | (1u << 10) | (16u << 17) | (8u << 24))
#define ID_F16 ((1u << 4) | (16u << 17) | (8u << 24))
#endif

// ---------------- producers (unchanged, passing) ----------------
__global__ void quant_x_kernel(const float* __restrict__ hs) {
    int t = blockIdx.x * blockDim.x + threadIdx.x;
    if (t >= S_LEN * D_DIM / 8) return;
    int idx = t * 8;
    int s = idx >> 12, d = idx & (D_DIM - 1);
    float4 v0 = *(const float4*)(hs + idx);
    float4 v1 = *(const float4*)(hs + idx + 4);
    int q0 = clampi(__float2int_rn(__fdiv_rn(v0.x, 0.1f)), -128, 127);
    int q1 = clampi(__float2int_rn(__fdiv_rn(v0.y, 0.1f)), -128, 127);
    int q2 = clampi(__float2int_rn(__fdiv_rn(v0.z, 0.1f)), -128, 127);
    int q3 = clampi(__float2int_rn(__fdiv_rn(v0.w, 0.1f)), -128, 127);
    int q4 = clampi(__float2int_rn(__fdiv_rn(v1.x, 0.1f)), -128, 127);
    int q5 = clampi(__float2int_rn(__fdiv_rn(v1.y, 0.1f)), -128, 127);
    int q6 = clampi(__float2int_rn(__fdiv_rn(v1.z, 0.1f)), -128, 127);
    int q7 = clampi(__float2int_rn(__fdiv_rn(v1.w, 0.1f)), -128, 127);
    int mt = s >> 7, r = s & 127, kt = d >> 6, c = d & 63;
    *(uint4*)((char*)g_xa + (((size_t)(mt * 64 + kt)) << 14) + sw_off(r, c)) =
        make_uint4(bfpack(q0, q1), bfpack(q2, q3), bfpack(q4, q5), bfpack(q6, q7));
}

__global__ void convert_w_kernel(const float* __restrict__ wq, const float* __restrict__ wk,
                                 const float* __restrict__ wv, const float* __restrict__ wo) {
    int t = blockIdx.x * blockDim.x + threadIdx.x;
    int z = blockIdx.y;
    if (t >= D_DIM * D_DIM / 8) return;
    const float* src = (z == 0) ? wq : (z == 1) ? wk : (z == 2) ? wv : wo;
    int idx = t * 8;
    int o = idx >> 12, k = idx & (D_DIM - 1);
    float4 v0 = *(const float4*)(src + idx);
    float4 v1 = *(const float4*)(src + idx + 4);
    int q0 = __float2int_rn(v0.x), q1 = __float2int_rn(v0.y);
    int q2 = __float2int_rn(v0.z), q3 = __float2int_rn(v0.w);
    int q4 = __float2int_rn(v1.x), q5 = __float2int_rn(v1.y);
    int q6 = __float2int_rn(v1.z), q7 = __float2int_rn(v1.w);
    int nt = o >> 7, r = o & 127, kt = k >> 6, c = k & 63;
    *(uint4*)((char*)g_wb[z] + (((size_t)(nt * 64 + kt)) << 14) + sw_off(r, c)) =
        make_uint4(bfpack(q0, q1), bfpack(q2, q3), bfpack(q4, q5), bfpack(q6, q7));
}

__global__ void rope_table_kernel(const int* __restrict__ pos) {
    int idx = blockIdx.x * blockDim.x + threadIdx.x;
    if (idx >= S_LEN * 64) return;
    int s = idx >> 6, i = idx & 63;
    float e = (float)(2 * i) * (1.0f / 128.0f);
    float powf32 = (float)pow(10000.0, (double)e);
    float invf = 1.0f / powf32;
    float ang = (float)pos[s] * invf;
    double a = (double)ang;
    g_rope[idx] = make_float2((float)cos(a), (float)sin(a));
}

__global__ void ropequant_qk_kernel(const float* __restrict__ sq, const float* __restrict__ sk) {
    int idx = blockIdx.x * blockDim.x + threadIdx.x;
    if (idx >= S_LEN * D_DIM) return;
    int s = idx >> 12, o = idx & (D_DIM - 1);
    int h = o >> 7, j = o & 127;
    float2 cs = g_rope[(s << 6) + (j & 63)];
    int o2 = (h << 7) + ((j < 64) ? (j + 64) : (j - 64));
    float sign = (j < 64) ? -1.0f : 1.0f;
    int base = s * D_DIM;
    size_t tile = ((size_t)(h * 16 + (s >> 7))) << 15;
    uint32_t off = ((uint32_t)(j >> 6) << 14) + sw_off(s & 127, j & 63);
    {
        float a = __fmul_rn((float)g_pint[0][base + o],  __fmul_rn(0.1f, sq[o]));
        float b = __fmul_rn((float)g_pint[0][base + o2], __fmul_rn(0.1f, sq[o2])) * sign;
        float r = __fadd_rn(__fmul_rn(a, cs.x), __fmul_rn(b, cs.y));
        int q = clampi(__float2int_rn(__fdiv_rn(r, 0.1f)), -128, 127);
        *(__nv_bfloat16*)((char*)g_qb + tile + off) = __float2bfloat16_rn((float)q);
    }
    {
        float a = __fmul_rn((float)g_pint[1][base + o],  __fmul_rn(0.1f, sk[o]));
        float b = __fmul_rn((float)g_pint[1][base + o2], __fmul_rn(0.1f, sk[o2])) * sign;
        float r = __fadd_rn(__fmul_rn(a, cs.x), __fmul_rn(b, cs.y));
        int q = clampi(__float2int_rn(__fdiv_rn(r, 0.1f)), -128, 127);
        *(__nv_bfloat16*)((char*)g_kb + tile + off) = __float2bfloat16_rn((float)q);
    }
}

__global__ void transpose_v_kernel(const float* __restrict__ sv) {
    __shared__ __half ts[32][136];
    int h = blockIdx.z, j0 = blockIdx.y * 32;
    int tid = threadIdx.x;
    int tx = tid & 31, ty = tid >> 5;
    int j = j0 + tx;
    float sc = __fmul_rn(0.1f, sv[h * 128 + j]);
    int s0 = blockIdx.x * 128;
    #pragma unroll
    for (int si = ty; si < 128; si += 8) {
        float a = __fmul_rn((float)g_pint[2][(s0 + si) * D_DIM + h * 128 + j], sc);
        int q = clampi(__float2int_rn(__fdiv_rn(a, 0.1f)), -128, 127);
        ts[tx][si] = __float2half_rn((float)q);
    }
    __syncthreads();
    char* base = (char*)g_vt + (((size_t)(h * 16 + blockIdx.x)) << 15);
    for (int e = tid; e < 32 * 16; e += 256) {
        int jj = e >> 4, sb = (e & 15) * 8;
        int d = j0 + jj;
        uint4 v;
        __half* hp = (__half*)&v;
        #pragma unroll
        for (int u = 0; u < 8; u++) hp[u] = ts[jj][sb + u];
        *(uint4*)(base + ((sb >> 6) << 14) + (uint32_t)((d * 128 + (sb & 63) * 2) ^ ((d & 7) << 4))) = v;
    }
}

// ---------------- tcgen05 GEMM (unchanged, passing) ----------------
#define NST 3
#define STG_B 65536
#define T_OFF_BAR 16
#define T_OFF_DONE 80
#define T_OFF_ST 1024
#define SMEM_TC (T_OFF_ST + NST * STG_B)

__global__ __launch_bounds__(128, 1) __cluster_dims__(1, 1, 1)
void gemm_tc_kernel(int mode, const float* __restrict__ so, float* __restrict__ out) {
#if USE_TC
    extern __shared__ __align__(1024) char sm[];
    uint32_t sb = smem_u32(sm);
    int tid = threadIdx.x, wid = tid >> 5, lid = tid & 31;
    const char* A; const char* B; int* C;
    if (mode == 0) { A = (const char*)g_xa; B = (const char*)g_wb[blockIdx.z]; C = g_pint[blockIdx.z]; }
    else           { A = (const char*)g_oa; B = (const char*)g_wb[3];          C = g_pint[0]; }
    int my = blockIdx.y, nt = blockIdx.x;
    if (wid == 0) { TCGEN05_ALLOC(sb, 512); TCGEN05_RELINQ(); }
    if (tid == 0) {
        #pragma unroll
        for (int s = 0; s < NST; s++) {
            MBARRIER_INIT(sb + T_OFF_BAR + s * 16, 1);
            MBARRIER_INIT(sb + T_OFF_BAR + s * 16 + 8, 1);
        }
        MBARRIER_INIT(sb + T_OFF_DONE, 1);
    }
    __syncthreads();
    uint32_t tmem;
    asm volatile("ld.shared.b32 %0, [%1];" : "=r"(tmem) : "r"(sb));
    const int KT = KDIM / 64;
    if (tid == 0) {
        for (int kt = 0; kt < KT; kt++) {
            int st = kt % NST, it = kt / NST;
            uint32_t fullb = sb + T_OFF_BAR + st * 16, emptyb = fullb + 8;
            if (kt >= NST) MBARRIER_WAIT_PARITY(emptyb, (it - 1) & 1);
            MBARRIER_EXPECT_TX(fullb, STG_B);
            uint32_t dst = sb + T_OFF_ST + st * STG_B;
            bulk_g2s(dst,         A + ((size_t)((2 * my)     * 64 + kt) << 14), 16384, fullb);
            bulk_g2s(dst + 16384, A + ((size_t)((2 * my + 1) * 64 + kt) << 14), 16384, fullb);
            bulk_g2s(dst + 32768, B + ((size_t)((2 * nt)     * 64 + kt) << 14), 16384, fullb);
            bulk_g2s(dst + 49152, B + ((size_t)((2 * nt + 1) * 64 + kt) << 14), 16384, fullb);
        }
    } else if (tid == 32) {
        for (int kt = 0; kt < KT; kt++) {
            int st = kt % NST, it = kt / NST;
            uint32_t fullb = sb + T_OFF_BAR + st * 16, emptyb = fullb + 8;
            MBARRIER_WAIT_PARITY(fullb, it & 1);
            uint32_t base = sb + T_OFF_ST + st * STG_B;
            uint64_t a0 = MAKE_SMEM_DESC(base);
            uint64_t a1 = MAKE_SMEM_DESC(base + 16384);
            uint64_t b0 = MAKE_SMEM_DESC(base + 32768);
            uint64_t b1 = MAKE_SMEM_DESC(base + 49152);
            #pragma unroll
            for (int sub = 0; sub < 4; sub++) {
                bool en = (kt > 0) || (sub > 0);
                mma_f16_ss(tmem,       a0 + sub * 2, b0 + sub * 2, ID_BF, en);
                mma_f16_ss(tmem + 128, a0 + sub * 2, b1 + sub * 2, ID_BF, en);
                mma_f16_ss(tmem + 256, a1 + sub * 2, b0 + sub * 2, ID_BF, en);
                mma_f16_ss(tmem + 384, a1 + sub * 2, b1 + sub * 2, ID_BF, en);
            }
            TCGEN05_COMMIT(emptyb);
        }
        TCGEN05_COMMIT(sb + T_OFF_DONE);
    }
    MBARRIER_WAIT_PARITY(sb + T_OFF_DONE, 0);
    TCGEN05_FENCE_AFTER();
    #pragma unroll
    for (int half = 0; half < 2; half++) {
        int mrow = my * 256 + half * 128 + wid * 32 + lid;
        #pragma unroll
        for (int hh = 0; hh < 2; hh++) {
            uint32_t tb = tmem + half * 256 + hh * 128;
            #pragma unroll
            for (int c0 = 0; c0 < 128; c0 += 32) {
                uint32_t r[32];
                TCGEN05_LD_X32(r, tb + c0);
                TCGEN05_WAIT_LD();
                if (mode == 0) {
                    int* Crow = C + (size_t)mrow * D_DIM + nt * 256 + hh * 128;
                    #pragma unroll
                    for (int j = 0; j < 32; j += 4)
                        *(int4*)(Crow + c0 + j) = make_int4(
                            __float2int_rn(__uint_as_float(r[j])), __float2int_rn(__uint_as_float(r[j + 1])),
                            __float2int_rn(__uint_as_float(r[j + 2])), __float2int_rn(__uint_as_float(r[j + 3])));
                } else {
                    float* Orow = out + (size_t)mrow * D_DIM + nt * 256 + hh * 128;
                    #pragma unroll
                    for (int j = 0; j < 32; j++)
                        Orow[c0 + j] = __fmul_rn(__uint_as_float(r[j]),
                                                 __fmul_rn(0.1f, so[nt * 256 + hh * 128 + c0 + j]));
                }
            }
        }
    }
    __syncthreads();
    if (wid == 0) TCGEN05_DEALLOC(tmem, 512);
#endif
}

// ---------------- tcgen05 flash attention: round-15 scheduling + fused EX2 softmax ----------------
#define A_Q 3072
#define A_K (A_Q + 32768)
#define A_V (A_K + 65536)
#define A_P (A_V + 65536)
#define SMEM_ATT (A_P + 65536)   // 232448

__global__ __launch_bounds__(256, 1) __cluster_dims__(1, 1, 1) void attn_kernel() {
#if USE_TC
    extern __shared__ __align__(1024) char sm[];
    uint32_t sb = smem_u32(sm);
    int qt = (int)gridDim.x - 1 - (int)blockIdx.x;
    int h = blockIdx.y;
    int tid = threadIdx.x, wid = tid >> 5, ln = tid & 31;
    int row = ((wid & 3) << 5) + ln;
    int ch = wid >> 2;
    uint32_t cbase = (uint32_t)ch * 64;
    float* red = (float*)(sm + A_P);
    const double SCd = (double)0.1f * (double)0.1f / 11.313708498984760390;
    const float C1 = (float)(SCd * 1.4426950408889634074);   // SC*log2(e)

    if (wid == 0) { TCGEN05_ALLOC(sb, 256); TCGEN05_RELINQ(); }
    if (tid == 0) { MBARRIER_INIT(sb + 16, 1); MBARRIER_INIT(sb + 24, 1); }
    __syncthreads();
    uint32_t tmem;
    asm volatile("ld.shared.b32 %0, [%1];" : "=r"(tmem) : "r"(sb));
    uint32_t tS = tmem, tO = tmem + 128;

    const char* Kg = (const char*)g_kb + (((size_t)(h * 16)) << 15);
    const char* Vg = (const char*)g_vt + (((size_t)(h * 16)) << 15);
    uint64_t qd = MAKE_SMEM_DESC(sb + A_Q);
    int nS = 0;

    // ===== pass A: exact row max =====
    {
        const char* Qg = (const char*)g_qb + (((size_t)(h * 16 + qt)) << 15);
        for (int i = tid; i < 2048; i += 256) cp_async16(sm + A_Q + i * 16, Qg + i * 16);
        for (int i = tid; i < 2048; i += 256) cp_async16(sm + A_K + i * 16, Kg + i * 16);
        cp_commit();
        const char* K1 = Kg + (((size_t)min(1, 15)) << 15);
        for (int i = tid; i < 2048; i += 256) cp_async16(sm + A_K + 32768 + i * 16, K1 + i * 16);
        cp_commit();
        asm volatile("cp.async.wait_group 1;\n");
        __syncthreads();
        if (tid == 0) {
            uint64_t kd = MAKE_SMEM_DESC(sb + A_K);
            #pragma unroll
            for (int kc = 0; kc < 2; kc++)
                #pragma unroll
                for (int s2 = 0; s2 < 4; s2++)
                    mma_f16_ss(tS, qd + kc * 1024 + s2 * 2, kd + kc * 1024 + s2 * 2, ID_BF, (kc | s2) != 0);
            TCGEN05_COMMIT(sb + 16);
        }
    }
    float Mf = -1e30f;
    for (int kt = 0; kt <= qt; kt++) {
        MBARRIER_WAIT_PARITY(sb + 16, nS & 1); nS++;
        TCGEN05_FENCE_AFTER();
        uint32_t r0[32], r1[32];
        TCGEN05_LD_X32(r0, tS + cbase);
        TCGEN05_LD_X32(r1, tS + cbase + 32);
        TCGEN05_WAIT_LD();
        TCGEN05_FENCE_BEFORE();
        {
            const char* src = Kg + (((size_t)min(kt + 2, 15)) << 15);
            char* dst = sm + A_K + (kt & 1) * 32768;
            for (int i = tid; i < 2048; i += 256) cp_async16(dst + i * 16, src + i * 16);
            cp_commit();
        }
        asm volatile("cp.async.wait_group 1;\n");
        __syncthreads();
        if (tid == 0 && kt < qt) {
            uint64_t kd = MAKE_SMEM_DESC(sb + A_K + ((kt + 1) & 1) * 32768);
            #pragma unroll
            for (int kc = 0; kc < 2; kc++)
                #pragma unroll
                for (int s2 = 0; s2 < 4; s2++)
                    mma_f16_ss(tS, qd + kc * 1024 + s2 * 2, kd + kc * 1024 + s2 * 2, ID_BF, (kc | s2) != 0);
            TCGEN05_COMMIT(sb + 16);
        }
        bool diag = (kt == qt);
        #pragma unroll
        for (int j = 0; j < 32; j++) {
            float v0 = __uint_as_float(r0[j]), v1 = __uint_as_float(r1[j]);
            if (!diag || (int)(cbase + j) <= row)      Mf = fmaxf(Mf, v0);
            if (!diag || (int)(cbase + 32 + j) <= row) Mf = fmaxf(Mf, v1);
        }
    }
    asm volatile("cp.async.wait_group 0;\n");
    __syncthreads();
    red[(ch << 7) + row] = Mf;
    __syncthreads();
    Mf = fmaxf(red[row], red[128 + row]);
    __syncthreads();
    const float c2 = __fmul_rn(-Mf, C1);
    float l = 0.0f;

    // ===== pass B =====
    for (int i = tid; i < 2048; i += 256) cp_async16(sm + A_K + i * 16, Kg + i * 16);
    for (int i = tid; i < 2048; i += 256) cp_async16(sm + A_V + i * 16, Vg + i * 16);
    cp_commit();
    {
        const char* K1 = Kg + (((size_t)min(1, 15)) << 15);
        for (int i = tid; i < 2048; i += 256) cp_async16(sm + A_K + 32768 + i * 16, K1 + i * 16);
        cp_commit();
    }
    asm volatile("cp.async.wait_group 0;\n");
    __syncthreads();
    if (tid == 0) {
        uint64_t kd = MAKE_SMEM_DESC(sb + A_K);
        #pragma unroll
        for (int kc = 0; kc < 2; kc++)
            #pragma unroll
            for (int s2 = 0; s2 < 4; s2++)
                mma_f16_ss(tS, qd + kc * 1024 + s2 * 2, kd + kc * 1024 + s2 * 2, ID_BF, (kc | s2) != 0);
        TCGEN05_COMMIT(sb + 16);
    }
    uint64_t pd = MAKE_SMEM_DESC(sb + A_P);
    uint64_t pld = MAKE_SMEM_DESC(sb + A_P + 32768);

    for (int kt = 0; kt <= qt; kt++) {
        MBARRIER_WAIT_PARITY(sb + 16, nS & 1); nS++;   // S(kt) done
        TCGEN05_FENCE_AFTER();
        uint32_t r0[32], r1[32];
        TCGEN05_LD_X32(r0, tS + cbase);
        TCGEN05_LD_X32(r1, tS + cbase + 32);
        TCGEN05_WAIT_LD();
        TCGEN05_FENCE_BEFORE();
        __syncthreads();
        if (tid == 0 && kt < qt) {                      // issue S(kt+1); softmax overlaps
            uint64_t kd = MAKE_SMEM_DESC(sb + A_K + ((kt + 1) & 1) * 32768);
            #pragma unroll
            for (int kc = 0; kc < 2; kc++)
                #pragma unroll
                for (int s2 = 0; s2 < 4; s2++)
                    mma_f16_ss(tS, qd + kc * 1024 + s2 * 2, kd + kc * 1024 + s2 * 2, ID_BF, (kc | s2) != 0);
            TCGEN05_COMMIT(sb + 16);
        }
        // softmax: p = ex2(fma(s, C1, c2))  (validated numerics)
        bool diag = (kt == qt);
        uint32_t ph[2][16], pl[2][16];
        #pragma unroll
        for (int b = 0; b < 2; b++) {
            const uint32_t* rr = (b == 0) ? r0 : r1;
            #pragma unroll
            for (int jj = 0; jj < 16; jj++) {
                int c = (int)cbase + b * 32 + 2 * jj;
                float p0 = 0.0f, p1 = 0.0f;
                if (!diag || c <= row)     p0 = ex2f(fmaf(__uint_as_float(rr[2 * jj]),     C1, c2));
                if (!diag || c + 1 <= row) p1 = ex2f(fmaf(__uint_as_float(rr[2 * jj + 1]), C1, c2));
                l += p0 + p1;
                splitpk2(p0, p1, ph[b][jj], pl[b][jj]);
            }
        }
        if (kt > 0) { MBARRIER_WAIT_PARITY(sb + 24, (kt - 1) & 1); TCGEN05_FENCE_AFTER(); }
        #pragma unroll
        for (int b = 0; b < 2; b++)
            #pragma unroll
            for (int g = 0; g < 4; g++) {
                uint32_t so2 = ((uint32_t)ch << 14) + sw_off(row, b * 32 + g * 8);
                *(uint4*)(sm + A_P + so2) =
                    make_uint4(ph[b][4 * g], ph[b][4 * g + 1], ph[b][4 * g + 2], ph[b][4 * g + 3]);
                *(uint4*)(sm + A_P + 32768 + so2) =
                    make_uint4(pl[b][4 * g], pl[b][4 * g + 1], pl[b][4 * g + 2], pl[b][4 * g + 3]);
            }
        FENCE_PROXY_ASYNC();
        if (kt < qt) {
            const char* vs = Vg + (((size_t)(kt + 1)) << 15);
            char* vd2 = sm + A_V + ((kt + 1) & 1) * 32768;
            for (int i = tid; i < 2048; i += 256) cp_async16(vd2 + i * 16, vs + i * 16);
            const char* ks = Kg + (((size_t)min(kt + 2, 15)) << 15);
            char* kd2 = sm + A_K + (kt & 1) * 32768;
            for (int i = tid; i < 2048; i += 256) cp_async16(kd2 + i * 16, ks + i * 16);
            cp_commit();
            asm volatile("cp.async.wait_group 1;\n");
        } else {
            asm volatile("cp.async.wait_group 0;\n");
        }
        __syncthreads();
        if (tid == 0) {
            uint64_t vd = MAKE_SMEM_DESC(sb + A_V + (kt & 1) * 32768);
            #pragma unroll
            for (int kc = 0; kc < 2; kc++)
                #pragma unroll
                for (int s2 = 0; s2 < 4; s2++) {
                    bool en = (kt > 0) || (kc | s2) != 0;
                    mma_f16_ss(tO, pd  + kc * 1024 + s2 * 2, vd + kc * 1024 + s2 * 2, ID_F16, en);
                    mma_f16_ss(tO, pld + kc * 1024 + s2 * 2, vd + kc * 1024 + s2 * 2, ID_F16, true);
                }
            TCGEN05_COMMIT(sb + 24);
        }
    }
    MBARRIER_WAIT_PARITY(sb + 24, qt & 1);
    TCGEN05_FENCE_AFTER();

    red[(ch << 7) + row] = l;
    __syncthreads();
    float lsum = red[row] + red[128 + row];

    int sg = qt * 128 + row;
    #pragma unroll
    for (int b = 0; b < 2; b++) {
        uint32_t r[32];
        TCGEN05_LD_X32(r, tO + cbase + b * 32);
        TCGEN05_WAIT_LD();
        #pragma unroll
        for (int jj = 0; jj < 16; jj++) {
            float x0 = __fmul_rn(__fdiv_rn(__uint_as_float(r[2 * jj]), lsum), 0.1f);
            float x1 = __fmul_rn(__fdiv_rn(__uint_as_float(r[2 * jj + 1]), lsum), 0.1f);
            int q0 = clampi(__float2int_rn(__fdiv_rn(x0, 0.1f)), -127, 127);
            int q1 = clampi(__float2int_rn(__fdiv_rn(x1, 0.1f)), -127, 127);
            int col = h * 128 + (int)cbase + b * 32 + 2 * jj;
            *(uint32_t*)((char*)g_oa + (((size_t)((sg >> 7) * 64 + (col >> 6))) << 14) + sw_off(sg & 127, col & 63)) =
                bfpack(q0, q1);
        }
    }
    __syncthreads();
    if (wid == 0) TCGEN05_DEALLOC(tmem, 256);
#endif
}

// ---------------- launch ----------------
extern "C" void kernel_launch(void* const* d_in, const int* in_sizes, int n_in,
                              void* d_out, int out_size) {
    const float* hs = (const float*)d_in[0];
    const float* wq = (const float*)d_in[1];
    const float* wk = (const float*)d_in[2];
    const float* wv = (const float*)d_in[3];
    const float* wo = (const float*)d_in[4];
    const float* sq = (const float*)d_in[5];
    const float* sk = (const float*)d_in[6];
    const float* sv = (const float*)d_in[7];
    const float* so = (const float*)d_in[8];
    const int*   pos = (const int*)d_in[10];
    float* out = (float*)d_out;

    cudaFuncSetAttribute(gemm_tc_kernel, cudaFuncAttributeMaxDynamicSharedMemorySize, SMEM_TC);
    cudaFuncSetAttribute(attn_kernel, cudaFuncAttributeMaxDynamicSharedMemorySize, SMEM_ATT);

    quant_x_kernel<<<(S_LEN * D_DIM / 8 + 255) / 256, 256>>>(hs);
    convert_w_kernel<<<dim3((D_DIM * D_DIM / 8 + 255) / 256, 4), 256>>>(wq, wk, wv, wo);
    rope_table_kernel<<<(S_LEN * 64 + 255) / 256, 256>>>(pos);

    gemm_tc_kernel<<<dim3(D_DIM / 256, S_LEN / 256, 3), 128, SMEM_TC>>>(0, so, out);   // QKV

    ropequant_qk_kernel<<<(S_LEN * D_DIM + 255) / 256, 256>>>(sq, sk);
    transpose_v_kernel<<<dim3(S_LEN / 128, 4, H_NUM), 256>>>(sv);

    attn_kernel<<<dim3(S_LEN / 128, H_NUM), 256, SMEM_ATT>>>();

    gemm_tc_kernel<<<dim3(D_DIM / 256, S_LEN / 256, 1), 128, SMEM_TC>>>(1, so, out);   // o-proj
}